// round 11
// baseline (speedup 1.0000x reference)
#include <cuda_runtime.h>
#include <cuda_fp16.h>
#include <math.h>

typedef unsigned int u32;
typedef unsigned short u16;

// ---------------------------------------------------------------------------
// ConvSlimCapsule3D via warp-level fp16 MMA (single-term, fp32 acc)
// + fast-math routing. Votes stored fp16.
// Conv: CTA = 64 pos x 128 oc, warp tile M32xN32, 3 CTAs/SM (24 warps/SM).
// x(2,8,16,32,32,32) w(128,16,3,3,3) cb(128) biases(8,16,1,1,1)
// ---------------------------------------------------------------------------

__device__ __half g_votesh[67108864];        // [b][pos][i*128+oc], 128 MB
// weights fp16: [tap=27][half=2][ic=16][oc=64]
__device__ __align__(16) __half g_wb2[55296];

// ---- SMEM layout (bytes) ----
// halo: 240 rows (4z x 10y x 6x) * 48B ; B: 8 warps * 2 bufs * (16 * 144B)
#define OFF_HH 0
#define OFF_B  11520
#define B_ROW  144           // 16B-aligned; 144%128=16 -> conflict-free
#define B_BUF  (16 * B_ROW)  // 2304
#define CONV_SMEM (11520 + 8 * 2 * B_BUF)   // 48384

__device__ __forceinline__ u32 smem_u32(const void* p) {
    u32 a;
    asm("{ .reg .u64 t; cvta.to.shared.u64 t, %1; cvt.u32.u64 %0, t; }"
        : "=r"(a) : "l"(p));
    return a;
}

#define LDSM_X4(r, a)                                                        \
    asm volatile("ldmatrix.sync.aligned.m8n8.x4.shared.b16 "                 \
                 "{%0,%1,%2,%3}, [%4];"                                      \
                 : "=r"((r)[0]), "=r"((r)[1]), "=r"((r)[2]), "=r"((r)[3])    \
                 : "r"(a))
#define LDSM_X4T(r0, r1, r2, r3, a)                                          \
    asm volatile("ldmatrix.sync.aligned.m8n8.x4.trans.shared.b16 "           \
                 "{%0,%1,%2,%3}, [%4];"                                      \
                 : "=r"(r0), "=r"(r1), "=r"(r2), "=r"(r3) : "r"(a))
#define MMA_F32(d, a, b)                                                     \
    asm volatile("mma.sync.aligned.m16n8k16.row.col.f32.f16.f16.f32 "       \
                 "{%0,%1,%2,%3}, {%4,%5,%6,%7}, {%8,%9}, {%0,%1,%2,%3};"    \
                 : "+f"((d)[0]), "+f"((d)[1]), "+f"((d)[2]), "+f"((d)[3])    \
                 : "r"((a)[0]), "r"((a)[1]), "r"((a)[2]), "r"((a)[3]),       \
                   "r"((b)[0]), "r"((b)[1]))

// ---------------- weight prep ----------------------------------------------
__global__ void build_wb_kernel(const float* __restrict__ w) {
    int idx = blockIdx.x * 256 + threadIdx.x;   // 55296 total
    if (idx >= 55296) return;
    int tap = idx >> 11;
    int r = idx & 2047;
    int half = r >> 10;
    int ic = (r >> 6) & 15;
    int oc = (half << 6) | (r & 63);
    g_wb2[idx] = __float2half_rn(w[oc * 432 + ic * 27 + tap]);
}

// ---------------- conv via warp MMA -----------------------------------------
// CTA: 64 positions (2z x 8y x 4x) x 128 oc. 8 warps: Wm=2 x Wn=4.
// Warp tile M32 x N32. A fp16, B fp16, fp32 accumulation.
__global__ __launch_bounds__(256, 3)
void conv_mma_kernel(const float* __restrict__ x, const float* __restrict__ cb) {
    extern __shared__ char sm[];
    const u32 smb = smem_u32(sm);
    const int tid = threadIdx.x;
    const int wid = tid >> 5, lane = tid & 31;
    const int n = blockIdx.y, b = n >> 3, i = n & 7;
    const int tile = blockIdx.x;                 // 512 tiles: 8x*4y*16z
    const int x0 = (tile & 7) * 4;
    const int y0 = ((tile >> 3) & 3) * 8;
    const int z0 = (tile >> 5) * 2;

    const int wm = (wid >> 2) * 32;              // M offset (0 or 32)
    const int q  = wid & 3;                      // oc quarter
    const int wn = q * 32;
    const u32 wbase = smb + OFF_B + (u32)wid * (2 * B_BUF);

    // ---- per-warp B staging: 2 x 16B per lane per tap (1KB/warp/tap) ----
    auto stage_tap = [&](int tap, int buf) {
        const __half* gsrc =
            g_wb2 + ((tap * 2 + (q >> 1)) << 10) + (q & 1) * 32;
#pragma unroll
        for (int t = lane; t < 64; t += 32) {
            int row = t >> 2, seg = t & 3;
            u32 d = wbase + (u32)buf * B_BUF + row * B_ROW + seg * 16;
            const __half* s = gsrc + row * 64 + seg * 8;
            asm volatile("cp.async.cg.shared.global [%0], [%1], 16;"
                         :: "r"(d), "l"(s));
        }
        asm volatile("cp.async.commit_group;" ::: "memory");
    };

    stage_tap(0, 0);

    // ---- halo tile: [240 rows = 4z*10y*6x][ic16] fp16, row stride 48B ----
    const float* xn = x + (size_t)n * 524288;
    for (int idx = tid; idx < 3840; idx += 256) {
        int ic = idx / 240, h = idx - ic * 240;
        int hz = h / 60, rp = h - hz * 60;
        int hy = rp / 6, hx = rp - hy * 6;
        int gz = z0 + hz - 1, gy = y0 + hy - 1, gx = x0 + hx - 1;
        float v = 0.0f;
        if ((unsigned)gz < 32u && (unsigned)gy < 32u && (unsigned)gx < 32u)
            v = xn[ic * 32768 + gz * 1024 + gy * 32 + gx];
        *(u16*)(sm + OFF_HH + h * 48 + ic * 2) =
            __half_as_ushort(__float2half_rn(v));
    }
    __syncthreads();   // the only CTA barrier before the epilogue

    // ---- per-lane ldmatrix addresses ----
    const int lr = lane & 15;
    const int ksel = (lane >> 4) * 16;
    u32 laddrA[2];
#pragma unroll
    for (int f = 0; f < 2; ++f) {
        int pos = wm + f * 16 + lr;                 // 0..63
        int lz = pos >> 5, ly = (pos >> 2) & 7, lx = pos & 3;
        laddrA[f] = smb + OFF_HH + (lz * 60 + ly * 6 + lx) * 48 + ksel;
    }
    u32 baddr[2];
#pragma unroll
    for (int p = 0; p < 2; ++p) {
        int ncloc = p * 16 + ((lane >> 4) & 1) * 8;
        baddr[p] = wbase + (lane & 15) * B_ROW + ncloc * 2;
    }

    float acc[2][4][4];
#pragma unroll
    for (int f = 0; f < 2; ++f)
#pragma unroll
        for (int nf = 0; nf < 4; ++nf)
#pragma unroll
            for (int qq = 0; qq < 4; ++qq) acc[f][nf][qq] = 0.0f;

#pragma unroll 1
    for (int tap = 0; tap < 27; ++tap) {
        if (tap + 1 < 27) {
            stage_tap(tap + 1, (tap + 1) & 1);
            asm volatile("cp.async.wait_group 1;" ::: "memory");
        } else {
            asm volatile("cp.async.wait_group 0;" ::: "memory");
        }
        __syncwarp();

        const int dz = tap / 9;
        const int rm = tap - dz * 9;
        const int dy = rm / 3, dx = rm - dy * 3;
        const u32 delta = (u32)((dz * 60 + dy * 6 + dx) * 48);

        u32 ah[2][4];
        LDSM_X4(ah[0], laddrA[0] + delta);
        LDSM_X4(ah[1], laddrA[1] + delta);

        const u32 bufo = (u32)((tap & 1) * B_BUF);
#pragma unroll
        for (int p = 0; p < 2; ++p) {
            u32 b0, b1, b2, b3;
            LDSM_X4T(b0, b1, b2, b3, baddr[p] + bufo);
            u32 bb0[2] = {b0, b1}, bb1[2] = {b2, b3};
#pragma unroll
            for (int f = 0; f < 2; ++f) {
                MMA_F32(acc[f][p * 2], ah[f], bb0);
                MMA_F32(acc[f][p * 2 + 1], ah[f], bb1);
            }
        }
    }

    // ---- epilogue: add conv bias, store fp16 votes ----
    float2 cbv[4];
#pragma unroll
    for (int nf = 0; nf < 4; ++nf)
        cbv[nf] = *(const float2*)(cb + wn + nf * 8 + (lane & 3) * 2);

#pragma unroll
    for (int f = 0; f < 2; ++f) {
#pragma unroll
        for (int hrow = 0; hrow < 2; ++hrow) {
            int pos = wm + f * 16 + (lane >> 2) + hrow * 8;
            int lz = pos >> 5, ly = (pos >> 2) & 7, lx = pos & 3;
            int gpos = (z0 + lz) * 1024 + (y0 + ly) * 32 + (x0 + lx);
            __half* vrow =
                g_votesh + (size_t)(b * 32768 + gpos) * 1024 + i * 128;
#pragma unroll
            for (int nf = 0; nf < 4; ++nf) {
                int col = wn + nf * 8 + (lane & 3) * 2;
                float ox = acc[f][nf][hrow * 2 + 0] + cbv[nf].x;
                float oy = acc[f][nf][hrow * 2 + 1] + cbv[nf].y;
                *(__half2*)(vrow + col) = __floats2half2_rn(ox, oy);
            }
        }
    }
}

// ---------------- Routing kernel (half2 regs, 4 CTAs/SM) --------------------
__global__ __launch_bounds__(256, 4)
void routing_kernel(const float* __restrict__ biases,
                    float* __restrict__ out) {
    __shared__ float sf[8 * 132];

    const int tid  = threadIdx.x;
    const int wrp  = tid >> 5;
    const int lane = tid & 31;
    const int o = lane >> 2;
    const int g = lane & 3;
    const int blk = blockIdx.x;
    const int b = blk >> 12;
    const int posbase = (blk & 4095) << 3;
    const int pos = posbase + wrp;

    const uint2* vp =
        (const uint2*)(g_votesh + (size_t)(b * 32768 + pos) * 1024);

    __half2 v2[8][2];
    float vnsq[8];
#pragma unroll
    for (int in = 0; in < 8; ++in) {
        uint2 raw = vp[in * 32 + o * 4 + g];
        v2[in][0] = *(__half2*)&raw.x;
        v2[in][1] = *(__half2*)&raw.y;
        float2 f01 = __half22float2(v2[in][0]);
        float2 f23 = __half22float2(v2[in][1]);
        float s = f01.x * f01.x + f01.y * f01.y +
                  f23.x * f23.x + f23.y * f23.y;
        s += __shfl_xor_sync(0xffffffffu, s, 1);
        s += __shfl_xor_sync(0xffffffffu, s, 2);
        vnsq[in] = s;
    }
    const float4 bs = ((const float4*)biases)[o * 4 + g];

    float logit[8];
#pragma unroll
    for (int in = 0; in < 8; ++in) logit[in] = 0.0f;

    float p0, p1, p2, p3;
    for (int it = 0; it < 3; ++it) {
        float route[8];
        if (it == 0) {
#pragma unroll
            for (int in = 0; in < 8; ++in) route[in] = 0.125f;
        } else {
#pragma unroll
            for (int in = 0; in < 8; ++in) {
                float e = __expf(logit[in]);
                float s = e;
                s += __shfl_xor_sync(0xffffffffu, s, 4);
                s += __shfl_xor_sync(0xffffffffu, s, 8);
                s += __shfl_xor_sync(0xffffffffu, s, 16);
                route[in] = __fdividef(e, s);
            }
        }
        p0 = bs.x; p1 = bs.y; p2 = bs.z; p3 = bs.w;
#pragma unroll
        for (int in = 0; in < 8; ++in) {
            float2 f01 = __half22float2(v2[in][0]);
            float2 f23 = __half22float2(v2[in][1]);
            p0 = fmaf(route[in], f01.x, p0);
            p1 = fmaf(route[in], f01.y, p1);
            p2 = fmaf(route[in], f23.x, p2);
            p3 = fmaf(route[in], f23.y, p3);
        }
        if (it < 2) {
            float pnsq = p0 * p0 + p1 * p1 + p2 * p2 + p3 * p3;
            pnsq += __shfl_xor_sync(0xffffffffu, pnsq, 1);
            pnsq += __shfl_xor_sync(0xffffffffu, pnsq, 2);
#pragma unroll
            for (int in = 0; in < 8; ++in) {
                float2 f01 = __half22float2(v2[in][0]);
                float2 f23 = __half22float2(v2[in][1]);
                float d = p0 * f01.x + p1 * f01.y + p2 * f23.x + p3 * f23.y;
                d += __shfl_xor_sync(0xffffffffu, d, 1);
                d += __shfl_xor_sync(0xffffffffu, d, 2);
                logit[in] = fmaf(
                    d, rsqrtf(fmaxf(pnsq * vnsq[in], 1e-16f)), logit[in]);
            }
        }
    }

    float nsq = p0 * p0 + p1 * p1 + p2 * p2 + p3 * p3;
    nsq += __shfl_xor_sync(0xffffffffu, nsq, 1);
    nsq += __shfl_xor_sync(0xffffffffu, nsq, 2);
    const float nrm = sqrtf(nsq);
    const float scale = __fdividef(nsq, (1.0f + nsq) * (nrm + 1e-12f));

    ((float4*)sf)[wrp * 33 + (o * 4 + g)] =
        make_float4(p0 * scale, p1 * scale, p2 * scale, p3 * scale);
    __syncthreads();

    for (int j = tid; j < 1024; j += 256) {
        const int oa = j >> 3;
        const int pp = j & 7;
        out[(size_t)(b * 128 + oa) * 32768 + posbase + pp] = sf[pp * 132 + oa];
    }
}

// ---------------- Launch -----------------------------------------------------
extern "C" void kernel_launch(void* const* d_in, const int* in_sizes, int n_in,
                              void* d_out, int out_size) {
    const float* x      = (const float*)d_in[0];
    const float* w      = (const float*)d_in[1];
    const float* cb     = (const float*)d_in[2];
    const float* biases = (const float*)d_in[3];
    float* out = (float*)d_out;

    build_wb_kernel<<<216, 256>>>(w);

    cudaFuncSetAttribute(conv_mma_kernel,
                         cudaFuncAttributeMaxDynamicSharedMemorySize,
                         CONV_SMEM);
    conv_mma_kernel<<<dim3(512, 16), 256, CONV_SMEM>>>(x, cb);
    routing_kernel<<<8192, 256>>>(biases, out);
}

// round 12
// speedup vs baseline: 1.0555x; 1.0555x over previous
#include <cuda_runtime.h>
#include <cuda_fp16.h>
#include <math.h>

typedef unsigned int u32;
typedef unsigned short u16;

// ---------------------------------------------------------------------------
// ConvSlimCapsule3D via warp-level fp16 MMA (single-term, fp32 acc)
// B operands loaded register-direct from fragment-ready gmem (no SMEM B).
// + fast-math routing. Votes stored fp16.
// x(2,8,16,32,32,32) w(128,16,3,3,3) cb(128) biases(8,16,1,1,1)
// ---------------------------------------------------------------------------

__device__ __half g_votesh[67108864];        // [b][pos][i*128+oc], 128 MB
// fragment-ready weights: [tap=27][half=2][lane=32][j=8][2] u32
__device__ __align__(16) u32 g_wfrag[27648];

// ---- SMEM: halo only: 400 rows * 48B ----
#define CONV_SMEM 19200

__device__ __forceinline__ u32 smem_u32(const void* p) {
    u32 a;
    asm("{ .reg .u64 t; cvta.to.shared.u64 t, %1; cvt.u32.u64 %0, t; }"
        : "=r"(a) : "l"(p));
    return a;
}

#define LDSM_X4(r, a)                                                        \
    asm volatile("ldmatrix.sync.aligned.m8n8.x4.shared.b16 "                 \
                 "{%0,%1,%2,%3}, [%4];"                                      \
                 : "=r"((r)[0]), "=r"((r)[1]), "=r"((r)[2]), "=r"((r)[3])    \
                 : "r"(a))
#define MMA_F32(d, a, b0, b1)                                                \
    asm volatile("mma.sync.aligned.m16n8k16.row.col.f32.f16.f16.f32 "       \
                 "{%0,%1,%2,%3}, {%4,%5,%6,%7}, {%8,%9}, {%0,%1,%2,%3};"    \
                 : "+f"((d)[0]), "+f"((d)[1]), "+f"((d)[2]), "+f"((d)[3])    \
                 : "r"((a)[0]), "r"((a)[1]), "r"((a)[2]), "r"((a)[3]),       \
                   "r"(b0), "r"(b1))

// ---------------- weight prep: fragment-ready layout -----------------------
// For mma.sync m16n8k16 row.col, lane l's B fragment for an 8-col block:
//   b0 = halves {B[2c][n], B[2c+1][n]}, b1 = {B[2c+8][n], B[2c+9][n]}
//   c = l&3, n = block_base + (l>>2);  B[k][n] = w[oc=n][ic=k][tap]
__global__ void build_wfrag_kernel(const float* __restrict__ w) {
    int idx = blockIdx.x * 256 + threadIdx.x;   // 13824 total
    if (idx >= 13824) return;
    int tap = idx >> 9;
    int r = idx & 511;
    int h = r >> 8;
    int lane = (r >> 3) & 31;
    int j = r & 7;
    int c = lane & 3;
    int n = h * 64 + j * 8 + (lane >> 2);
    const float* wn = w + n * 432 + tap;        // + ic*27
    __half a0 = __float2half_rn(wn[(2 * c) * 27]);
    __half a1 = __float2half_rn(wn[(2 * c + 1) * 27]);
    __half a2 = __float2half_rn(wn[(2 * c + 8) * 27]);
    __half a3 = __float2half_rn(wn[(2 * c + 9) * 27]);
    u32 base = (u32)(((tap * 2 + h) * 32 + lane) * 16 + j * 2);
    g_wfrag[base]     = (u32)__half_as_ushort(a0) |
                        ((u32)__half_as_ushort(a1) << 16);
    g_wfrag[base + 1] = (u32)__half_as_ushort(a2) |
                        ((u32)__half_as_ushort(a3) << 16);
}

// ---------------- conv via warp MMA -----------------------------------------
// CTA: 128 positions (2z x 8y x 8x) x 128 oc. 8 warps: Wm=4 x Wn=2.
// A fp16 via ldmatrix from halo; B fp16 register-direct LDG.128 x4 per tap,
// double-buffered in registers across taps.
__global__ __launch_bounds__(256, 2)
void conv_mma_kernel(const float* __restrict__ x, const float* __restrict__ cb) {
    extern __shared__ char sm[];
    const u32 smb = smem_u32(sm);
    const int tid = threadIdx.x;
    const int wid = tid >> 5, lane = tid & 31;
    const int n = blockIdx.y, b = n >> 3, i = n & 7;
    const int tile = blockIdx.x;                 // 256 tiles: 4x*4y*16z
    const int x0 = (tile & 3) * 8;
    const int y0 = ((tile >> 2) & 3) * 8;
    const int z0 = (tile >> 4) * 2;

    const int wm = (wid >> 1) * 32;
    const int half = wid & 1;                    // oc half
    const int wn = half * 64;

    // ---- halo tile: [400 rows][ic16] fp16, row stride 48B ----
    const float* xn = x + (size_t)n * 524288;
    for (int idx = tid; idx < 6400; idx += 256) {
        int ic = idx / 400, h = idx - ic * 400;
        int hz = h / 100, rp = h - hz * 100;
        int hy = rp / 10, hx = rp - hy * 10;
        int gz = z0 + hz - 1, gy = y0 + hy - 1, gx = x0 + hx - 1;
        float v = 0.0f;
        if ((unsigned)gz < 32u && (unsigned)gy < 32u && (unsigned)gx < 32u)
            v = xn[ic * 32768 + gz * 1024 + gy * 32 + gx];
        *(u16*)(sm + h * 48 + ic * 2) =
            __half_as_ushort(__float2half_rn(v));
    }
    __syncthreads();   // the only CTA barrier before the epilogue

    // ---- per-lane ldmatrix A addresses ----
    const int lr = lane & 15;
    const int ksel = (lane >> 4) * 16;
    u32 laddrA[2];
#pragma unroll
    for (int f = 0; f < 2; ++f) {
        int pos = wm + f * 16 + lr;
        int lz = pos >> 6, ly = (pos >> 3) & 7, lx = pos & 7;
        laddrA[f] = smb + (lz * 100 + ly * 10 + lx) * 48 + ksel;
    }

    // ---- B fragment pointer: per (half, lane), stride 1024 u32 per tap ----
    const uint4* wfp =
        (const uint4*)(g_wfrag + ((u32)half * 32 + lane) * 16);
    // per-tap stride in uint4 units: 1024/4 = 256

    float acc[2][8][4];
#pragma unroll
    for (int f = 0; f < 2; ++f)
#pragma unroll
        for (int nf = 0; nf < 8; ++nf)
#pragma unroll
            for (int q = 0; q < 4; ++q) acc[f][nf][q] = 0.0f;

    uint4 cur[4];
#pragma unroll
    for (int q = 0; q < 4; ++q) cur[q] = __ldg(wfp + q);

#pragma unroll 1
    for (int tap = 0; tap < 27; ++tap) {
        // prefetch next tap's B fragments (clamped; tap 26 reloads itself)
        const int ntap = (tap + 1 < 27) ? tap + 1 : 26;
        uint4 nxt[4];
#pragma unroll
        for (int q = 0; q < 4; ++q)
            nxt[q] = __ldg(wfp + ntap * 256 + q);

        const int dz = tap / 9;
        const int rm = tap - dz * 9;
        const int dy = rm / 3, dx = rm - dy * 3;
        const u32 delta = (u32)((dz * 100 + dy * 10 + dx) * 48);

        u32 ah[2][4];
        LDSM_X4(ah[0], laddrA[0] + delta);
        LDSM_X4(ah[1], laddrA[1] + delta);

#pragma unroll
        for (int p = 0; p < 4; ++p) {
#pragma unroll
            for (int f = 0; f < 2; ++f) {
                MMA_F32(acc[f][p * 2],     ah[f], cur[p].x, cur[p].y);
                MMA_F32(acc[f][p * 2 + 1], ah[f], cur[p].z, cur[p].w);
            }
        }
#pragma unroll
        for (int q = 0; q < 4; ++q) cur[q] = nxt[q];
    }

    // ---- epilogue: add conv bias, store fp16 votes ----
    float2 cbv[8];
#pragma unroll
    for (int nf = 0; nf < 8; ++nf)
        cbv[nf] = *(const float2*)(cb + wn + nf * 8 + (lane & 3) * 2);

#pragma unroll
    for (int f = 0; f < 2; ++f) {
        int pos0 = wm + f * 16 + (lane >> 2);
#pragma unroll
        for (int hrow = 0; hrow < 2; ++hrow) {
            int pos = pos0 + hrow * 8;
            int lz = pos >> 6, ly = (pos >> 3) & 7, lx = pos & 7;
            int gpos = (z0 + lz) * 1024 + (y0 + ly) * 32 + (x0 + lx);
            __half* vrow =
                g_votesh + (size_t)(b * 32768 + gpos) * 1024 + i * 128;
#pragma unroll
            for (int nf = 0; nf < 8; ++nf) {
                int col = wn + nf * 8 + (lane & 3) * 2;
                float ox = acc[f][nf][hrow * 2 + 0] + cbv[nf].x;
                float oy = acc[f][nf][hrow * 2 + 1] + cbv[nf].y;
                *(__half2*)(vrow + col) = __floats2half2_rn(ox, oy);
            }
        }
    }
}

// ---------------- Routing kernel (half2 regs, 4 CTAs/SM) --------------------
__global__ __launch_bounds__(256, 4)
void routing_kernel(const float* __restrict__ biases,
                    float* __restrict__ out) {
    __shared__ float sf[8 * 132];

    const int tid  = threadIdx.x;
    const int wrp  = tid >> 5;
    const int lane = tid & 31;
    const int o = lane >> 2;
    const int g = lane & 3;
    const int blk = blockIdx.x;
    const int b = blk >> 12;
    const int posbase = (blk & 4095) << 3;
    const int pos = posbase + wrp;

    const uint2* vp =
        (const uint2*)(g_votesh + (size_t)(b * 32768 + pos) * 1024);

    __half2 v2[8][2];
    float vnsq[8];
#pragma unroll
    for (int in = 0; in < 8; ++in) {
        uint2 raw = vp[in * 32 + o * 4 + g];
        v2[in][0] = *(__half2*)&raw.x;
        v2[in][1] = *(__half2*)&raw.y;
        float2 f01 = __half22float2(v2[in][0]);
        float2 f23 = __half22float2(v2[in][1]);
        float s = f01.x * f01.x + f01.y * f01.y +
                  f23.x * f23.x + f23.y * f23.y;
        s += __shfl_xor_sync(0xffffffffu, s, 1);
        s += __shfl_xor_sync(0xffffffffu, s, 2);
        vnsq[in] = s;
    }
    const float4 bs = ((const float4*)biases)[o * 4 + g];

    float logit[8];
#pragma unroll
    for (int in = 0; in < 8; ++in) logit[in] = 0.0f;

    float p0, p1, p2, p3;
    for (int it = 0; it < 3; ++it) {
        float route[8];
        if (it == 0) {
#pragma unroll
            for (int in = 0; in < 8; ++in) route[in] = 0.125f;
        } else {
#pragma unroll
            for (int in = 0; in < 8; ++in) {
                float e = __expf(logit[in]);
                float s = e;
                s += __shfl_xor_sync(0xffffffffu, s, 4);
                s += __shfl_xor_sync(0xffffffffu, s, 8);
                s += __shfl_xor_sync(0xffffffffu, s, 16);
                route[in] = __fdividef(e, s);
            }
        }
        p0 = bs.x; p1 = bs.y; p2 = bs.z; p3 = bs.w;
#pragma unroll
        for (int in = 0; in < 8; ++in) {
            float2 f01 = __half22float2(v2[in][0]);
            float2 f23 = __half22float2(v2[in][1]);
            p0 = fmaf(route[in], f01.x, p0);
            p1 = fmaf(route[in], f01.y, p1);
            p2 = fmaf(route[in], f23.x, p2);
            p3 = fmaf(route[in], f23.y, p3);
        }
        if (it < 2) {
            float pnsq = p0 * p0 + p1 * p1 + p2 * p2 + p3 * p3;
            pnsq += __shfl_xor_sync(0xffffffffu, pnsq, 1);
            pnsq += __shfl_xor_sync(0xffffffffu, pnsq, 2);
#pragma unroll
            for (int in = 0; in < 8; ++in) {
                float2 f01 = __half22float2(v2[in][0]);
                float2 f23 = __half22float2(v2[in][1]);
                float d = p0 * f01.x + p1 * f01.y + p2 * f23.x + p3 * f23.y;
                d += __shfl_xor_sync(0xffffffffu, d, 1);
                d += __shfl_xor_sync(0xffffffffu, d, 2);
                logit[in] = fmaf(
                    d, rsqrtf(fmaxf(pnsq * vnsq[in], 1e-16f)), logit[in]);
            }
        }
    }

    float nsq = p0 * p0 + p1 * p1 + p2 * p2 + p3 * p3;
    nsq += __shfl_xor_sync(0xffffffffu, nsq, 1);
    nsq += __shfl_xor_sync(0xffffffffu, nsq, 2);
    const float nrm = sqrtf(nsq);
    const float scale = __fdividef(nsq, (1.0f + nsq) * (nrm + 1e-12f));

    ((float4*)sf)[wrp * 33 + (o * 4 + g)] =
        make_float4(p0 * scale, p1 * scale, p2 * scale, p3 * scale);
    __syncthreads();

    for (int j = tid; j < 1024; j += 256) {
        const int oa = j >> 3;
        const int pp = j & 7;
        out[(size_t)(b * 128 + oa) * 32768 + posbase + pp] = sf[pp * 132 + oa];
    }
}

// ---------------- Launch -----------------------------------------------------
extern "C" void kernel_launch(void* const* d_in, const int* in_sizes, int n_in,
                              void* d_out, int out_size) {
    const float* x      = (const float*)d_in[0];
    const float* w      = (const float*)d_in[1];
    const float* cb     = (const float*)d_in[2];
    const float* biases = (const float*)d_in[3];
    float* out = (float*)d_out;

    build_wfrag_kernel<<<54, 256>>>(w);

    cudaFuncSetAttribute(conv_mma_kernel,
                         cudaFuncAttributeMaxDynamicSharedMemorySize,
                         CONV_SMEM);
    conv_mma_kernel<<<dim3(256, 16), 256, CONV_SMEM>>>(x, cb);
    routing_kernel<<<8192, 256>>>(biases, out);
}

// round 13
// speedup vs baseline: 1.2433x; 1.1779x over previous
#include <cuda_runtime.h>
#include <cuda_fp16.h>
#include <math.h>

typedef unsigned int u32;
typedef unsigned short u16;

// ---------------------------------------------------------------------------
// ConvSlimCapsule3D via warp-level fp16 MMA (single-term, fp32 acc)
// + fast-math routing. Votes stored fp16. B pipeline: 4-deep per-warp cp.async.
// x(2,8,16,32,32,32) w(128,16,3,3,3) cb(128) biases(8,16,1,1,1)
// ---------------------------------------------------------------------------

__device__ __half g_votesh[67108864];        // [b][pos][i*128+oc], 128 MB
// weights fp16: [tap=27][half=2][ic=16][oc=64]
__device__ __align__(16) __half g_wb2[55296];

// ---- SMEM layout (bytes) ----
#define OFF_HH 0
#define OFF_B  19200
#define B_ROW  144           // 16B-aligned rows; 144%128=16 -> conflict-free
#define B_BUF  (16 * B_ROW)  // 2304
#define NBUF   4
#define CONV_SMEM (19200 + 8 * NBUF * B_BUF)   // 92928

__device__ __forceinline__ u32 smem_u32(const void* p) {
    u32 a;
    asm("{ .reg .u64 t; cvta.to.shared.u64 t, %1; cvt.u32.u64 %0, t; }"
        : "=r"(a) : "l"(p));
    return a;
}

#define LDSM_X4(r, a)                                                        \
    asm volatile("ldmatrix.sync.aligned.m8n8.x4.shared.b16 "                 \
                 "{%0,%1,%2,%3}, [%4];"                                      \
                 : "=r"((r)[0]), "=r"((r)[1]), "=r"((r)[2]), "=r"((r)[3])    \
                 : "r"(a))
#define LDSM_X4T(r0, r1, r2, r3, a)                                          \
    asm volatile("ldmatrix.sync.aligned.m8n8.x4.trans.shared.b16 "           \
                 "{%0,%1,%2,%3}, [%4];"                                      \
                 : "=r"(r0), "=r"(r1), "=r"(r2), "=r"(r3) : "r"(a))
#define MMA_F32(d, a, b)                                                     \
    asm volatile("mma.sync.aligned.m16n8k16.row.col.f32.f16.f16.f32 "       \
                 "{%0,%1,%2,%3}, {%4,%5,%6,%7}, {%8,%9}, {%0,%1,%2,%3};"    \
                 : "+f"((d)[0]), "+f"((d)[1]), "+f"((d)[2]), "+f"((d)[3])    \
                 : "r"((a)[0]), "r"((a)[1]), "r"((a)[2]), "r"((a)[3]),       \
                   "r"((b)[0]), "r"((b)[1]))

// ---------------- weight prep ----------------------------------------------
__global__ void build_wb_kernel(const float* __restrict__ w) {
    int idx = blockIdx.x * 256 + threadIdx.x;   // 55296 total
    if (idx >= 55296) return;
    int tap = idx >> 11;
    int r = idx & 2047;
    int half = r >> 10;
    int ic = (r >> 6) & 15;
    int oc = (half << 6) | (r & 63);
    g_wb2[idx] = __float2half_rn(w[oc * 432 + ic * 27 + tap]);
}

// ---------------- conv via warp MMA -----------------------------------------
// CTA: 128 positions (2z x 8y x 8x) x 128 oc. 8 warps: Wm=4 x Wn=2.
// A fp16, B fp16, fp32 accumulation. 4-deep per-warp B pipeline:
// prologue stages taps 0-2; steady state waits group<=2 (distance-3 prefetch).
__global__ __launch_bounds__(256, 2)
void conv_mma_kernel(const float* __restrict__ x, const float* __restrict__ cb) {
    extern __shared__ char sm[];
    const u32 smb = smem_u32(sm);
    const int tid = threadIdx.x;
    const int wid = tid >> 5, lane = tid & 31;
    const int n = blockIdx.y, b = n >> 3, i = n & 7;
    const int tile = blockIdx.x;                 // 256 tiles: 4x*4y*16z
    const int x0 = (tile & 3) * 8;
    const int y0 = ((tile >> 2) & 3) * 8;
    const int z0 = (tile >> 4) * 2;

    const int wm = (wid >> 1) * 32;
    const int half = wid & 1;                    // oc half
    const int wn = half * 64;
    const u32 wbase = smb + OFF_B + (u32)wid * (NBUF * B_BUF);

    // ---- per-warp B staging: 4 x 16B per lane per tap ----
    const int srow0 = lane >> 3, sseg = lane & 7;
    auto stage_tap = [&](int tap, int buf) {
        const __half* gsrc = g_wb2 + ((tap * 2 + half) << 10);
#pragma unroll
        for (int j = 0; j < 4; ++j) {
            int row = srow0 + j * 4;
            u32 d = wbase + (u32)buf * B_BUF + row * B_ROW + sseg * 16;
            const __half* s = gsrc + row * 64 + sseg * 8;
            asm volatile("cp.async.cg.shared.global [%0], [%1], 16;"
                         :: "r"(d), "l"(s));
        }
        asm volatile("cp.async.commit_group;" ::: "memory");
    };

    stage_tap(0, 0);
    stage_tap(1, 1);
    stage_tap(2, 2);

    // ---- halo tile: [400 rows][ic16] fp16, row stride 48B ----
    const float* xn = x + (size_t)n * 524288;
    for (int idx = tid; idx < 6400; idx += 256) {
        int ic = idx / 400, h = idx - ic * 400;
        int hz = h / 100, rp = h - hz * 100;
        int hy = rp / 10, hx = rp - hy * 10;
        int gz = z0 + hz - 1, gy = y0 + hy - 1, gx = x0 + hx - 1;
        float v = 0.0f;
        if ((unsigned)gz < 32u && (unsigned)gy < 32u && (unsigned)gx < 32u)
            v = xn[ic * 32768 + gz * 1024 + gy * 32 + gx];
        *(u16*)(sm + OFF_HH + h * 48 + ic * 2) =
            __half_as_ushort(__float2half_rn(v));
    }
    __syncthreads();   // the only CTA barrier before the epilogue

    // ---- per-lane ldmatrix addresses ----
    const int lr = lane & 15;
    const int ksel = (lane >> 4) * 16;
    u32 laddrA[2];
#pragma unroll
    for (int f = 0; f < 2; ++f) {
        int pos = wm + f * 16 + lr;
        int lz = pos >> 6, ly = (pos >> 3) & 7, lx = pos & 7;
        laddrA[f] = smb + OFF_HH + (lz * 100 + ly * 10 + lx) * 48 + ksel;
    }
    u32 baddr[4];
#pragma unroll
    for (int p = 0; p < 4; ++p) {
        int ncloc = p * 16 + ((lane >> 4) & 1) * 8;
        baddr[p] = wbase + (lane & 15) * B_ROW + ncloc * 2;
    }

    float acc[2][8][4];
#pragma unroll
    for (int f = 0; f < 2; ++f)
#pragma unroll
        for (int nf = 0; nf < 8; ++nf)
#pragma unroll
            for (int q = 0; q < 4; ++q) acc[f][nf][q] = 0.0f;

#pragma unroll 1
    for (int tap = 0; tap < 27; ++tap) {
        // ensure tap's group is complete (distance-3 prefetch)
        if (tap < 25) {
            asm volatile("cp.async.wait_group 2;" ::: "memory");
        } else if (tap == 25) {
            asm volatile("cp.async.wait_group 1;" ::: "memory");
        } else {
            asm volatile("cp.async.wait_group 0;" ::: "memory");
        }
        __syncwarp();

        const int dz = tap / 9;
        const int rm = tap - dz * 9;
        const int dy = rm / 3, dx = rm - dy * 3;
        const u32 delta = (u32)((dz * 100 + dy * 10 + dx) * 48);

        u32 ah[2][4];
        LDSM_X4(ah[0], laddrA[0] + delta);
        LDSM_X4(ah[1], laddrA[1] + delta);

        const u32 bufo = (u32)((tap & 3) * B_BUF);
#pragma unroll
        for (int p = 0; p < 4; ++p) {
            u32 b0, b1, b2, b3;
            LDSM_X4T(b0, b1, b2, b3, baddr[p] + bufo);
            u32 bb0[2] = {b0, b1}, bb1[2] = {b2, b3};
#pragma unroll
            for (int f = 0; f < 2; ++f) {
                MMA_F32(acc[f][p * 2], ah[f], bb0);
                MMA_F32(acc[f][p * 2 + 1], ah[f], bb1);
            }
        }

        // stage tap+3 into the buffer freed by tap-1 (consumed last iter)
        if (tap + 3 < 27) stage_tap(tap + 3, (tap + 3) & 3);
    }

    // ---- epilogue: add conv bias, store fp16 votes ----
    float2 cbv[8];
#pragma unroll
    for (int nf = 0; nf < 8; ++nf)
        cbv[nf] = *(const float2*)(cb + wn + nf * 8 + (lane & 3) * 2);

#pragma unroll
    for (int f = 0; f < 2; ++f) {
        int pos0 = wm + f * 16 + (lane >> 2);
#pragma unroll
        for (int hrow = 0; hrow < 2; ++hrow) {
            int pos = pos0 + hrow * 8;
            int lz = pos >> 6, ly = (pos >> 3) & 7, lx = pos & 7;
            int gpos = (z0 + lz) * 1024 + (y0 + ly) * 32 + (x0 + lx);
            __half* vrow =
                g_votesh + (size_t)(b * 32768 + gpos) * 1024 + i * 128;
#pragma unroll
            for (int nf = 0; nf < 8; ++nf) {
                int col = wn + nf * 8 + (lane & 3) * 2;
                float ox = acc[f][nf][hrow * 2 + 0] + cbv[nf].x;
                float oy = acc[f][nf][hrow * 2 + 1] + cbv[nf].y;
                *(__half2*)(vrow + col) = __floats2half2_rn(ox, oy);
            }
        }
    }
}

// ---------------- Routing kernel (half2 regs, 4 CTAs/SM) --------------------
__global__ __launch_bounds__(256, 4)
void routing_kernel(const float* __restrict__ biases,
                    float* __restrict__ out) {
    __shared__ float sf[8 * 132];

    const int tid  = threadIdx.x;
    const int wrp  = tid >> 5;
    const int lane = tid & 31;
    const int o = lane >> 2;
    const int g = lane & 3;
    const int blk = blockIdx.x;
    const int b = blk >> 12;
    const int posbase = (blk & 4095) << 3;
    const int pos = posbase + wrp;

    const uint2* vp =
        (const uint2*)(g_votesh + (size_t)(b * 32768 + pos) * 1024);

    __half2 v2[8][2];
    float vnsq[8];
#pragma unroll
    for (int in = 0; in < 8; ++in) {
        uint2 raw = vp[in * 32 + o * 4 + g];
        v2[in][0] = *(__half2*)&raw.x;
        v2[in][1] = *(__half2*)&raw.y;
        float2 f01 = __half22float2(v2[in][0]);
        float2 f23 = __half22float2(v2[in][1]);
        float s = f01.x * f01.x + f01.y * f01.y +
                  f23.x * f23.x + f23.y * f23.y;
        s += __shfl_xor_sync(0xffffffffu, s, 1);
        s += __shfl_xor_sync(0xffffffffu, s, 2);
        vnsq[in] = s;
    }
    const float4 bs = ((const float4*)biases)[o * 4 + g];

    float logit[8];
#pragma unroll
    for (int in = 0; in < 8; ++in) logit[in] = 0.0f;

    float p0, p1, p2, p3;
    for (int it = 0; it < 3; ++it) {
        float route[8];
        if (it == 0) {
#pragma unroll
            for (int in = 0; in < 8; ++in) route[in] = 0.125f;
        } else {
#pragma unroll
            for (int in = 0; in < 8; ++in) {
                float e = __expf(logit[in]);
                float s = e;
                s += __shfl_xor_sync(0xffffffffu, s, 4);
                s += __shfl_xor_sync(0xffffffffu, s, 8);
                s += __shfl_xor_sync(0xffffffffu, s, 16);
                route[in] = __fdividef(e, s);
            }
        }
        p0 = bs.x; p1 = bs.y; p2 = bs.z; p3 = bs.w;
#pragma unroll
        for (int in = 0; in < 8; ++in) {
            float2 f01 = __half22float2(v2[in][0]);
            float2 f23 = __half22float2(v2[in][1]);
            p0 = fmaf(route[in], f01.x, p0);
            p1 = fmaf(route[in], f01.y, p1);
            p2 = fmaf(route[in], f23.x, p2);
            p3 = fmaf(route[in], f23.y, p3);
        }
        if (it < 2) {
            float pnsq = p0 * p0 + p1 * p1 + p2 * p2 + p3 * p3;
            pnsq += __shfl_xor_sync(0xffffffffu, pnsq, 1);
            pnsq += __shfl_xor_sync(0xffffffffu, pnsq, 2);
#pragma unroll
            for (int in = 0; in < 8; ++in) {
                float2 f01 = __half22float2(v2[in][0]);
                float2 f23 = __half22float2(v2[in][1]);
                float d = p0 * f01.x + p1 * f01.y + p2 * f23.x + p3 * f23.y;
                d += __shfl_xor_sync(0xffffffffu, d, 1);
                d += __shfl_xor_sync(0xffffffffu, d, 2);
                logit[in] = fmaf(
                    d, rsqrtf(fmaxf(pnsq * vnsq[in], 1e-16f)), logit[in]);
            }
        }
    }

    float nsq = p0 * p0 + p1 * p1 + p2 * p2 + p3 * p3;
    nsq += __shfl_xor_sync(0xffffffffu, nsq, 1);
    nsq += __shfl_xor_sync(0xffffffffu, nsq, 2);
    const float nrm = sqrtf(nsq);
    const float scale = __fdividef(nsq, (1.0f + nsq) * (nrm + 1e-12f));

    ((float4*)sf)[wrp * 33 + (o * 4 + g)] =
        make_float4(p0 * scale, p1 * scale, p2 * scale, p3 * scale);
    __syncthreads();

    for (int j = tid; j < 1024; j += 256) {
        const int oa = j >> 3;
        const int pp = j & 7;
        out[(size_t)(b * 128 + oa) * 32768 + posbase + pp] = sf[pp * 132 + oa];
    }
}

// ---------------- Launch -----------------------------------------------------
extern "C" void kernel_launch(void* const* d_in, const int* in_sizes, int n_in,
                              void* d_out, int out_size) {
    const float* x      = (const float*)d_in[0];
    const float* w      = (const float*)d_in[1];
    const float* cb     = (const float*)d_in[2];
    const float* biases = (const float*)d_in[3];
    float* out = (float*)d_out;

    build_wb_kernel<<<216, 256>>>(w);

    cudaFuncSetAttribute(conv_mma_kernel,
                         cudaFuncAttributeMaxDynamicSharedMemorySize,
                         CONV_SMEM);
    conv_mma_kernel<<<dim3(256, 16), 256, CONV_SMEM>>>(x, cb);
    routing_kernel<<<8192, 256>>>(biases, out);
}

// round 14
// speedup vs baseline: 1.4235x; 1.1449x over previous
#include <cuda_runtime.h>
#include <cuda_fp16.h>
#include <math.h>

typedef unsigned int u32;
typedef unsigned short u16;

// ---------------------------------------------------------------------------
// ConvSlimCapsule3D via warp-level fp16 MMA (single-term, fp32 acc)
// + fast-math routing. Votes stored fp16. B pipeline: 4-deep per-warp cp.async.
// Epilogue: SMEM transpose -> coalesced STG.128 vote stores.
// x(2,8,16,32,32,32) w(128,16,3,3,3) cb(128) biases(8,16,1,1,1)
// ---------------------------------------------------------------------------

__device__ __half g_votesh[67108864];        // [b][pos][i*128+oc], 128 MB
// weights fp16: [tap=27][half=2][ic=16][oc=64]
__device__ __align__(16) __half g_wb2[55296];

// ---- SMEM layout (bytes) ----
#define OFF_HH 0
#define OFF_B  19200
#define B_ROW  144           // 16B-aligned rows; 144%128=16 -> conflict-free
#define B_BUF  (16 * B_ROW)  // 2304
#define NBUF   4
#define CONV_SMEM (19200 + 8 * NBUF * B_BUF)   // 92928
// epilogue staging reuses [OFF_B, OFF_B+34816): 128 rows * 272B

__device__ __forceinline__ u32 smem_u32(const void* p) {
    u32 a;
    asm("{ .reg .u64 t; cvta.to.shared.u64 t, %1; cvt.u32.u64 %0, t; }"
        : "=r"(a) : "l"(p));
    return a;
}

#define LDSM_X4(r, a)                                                        \
    asm volatile("ldmatrix.sync.aligned.m8n8.x4.shared.b16 "                 \
                 "{%0,%1,%2,%3}, [%4];"                                      \
                 : "=r"((r)[0]), "=r"((r)[1]), "=r"((r)[2]), "=r"((r)[3])    \
                 : "r"(a))
#define LDSM_X4T(r0, r1, r2, r3, a)                                          \
    asm volatile("ldmatrix.sync.aligned.m8n8.x4.trans.shared.b16 "           \
                 "{%0,%1,%2,%3}, [%4];"                                      \
                 : "=r"(r0), "=r"(r1), "=r"(r2), "=r"(r3) : "r"(a))
#define MMA_F32(d, a, b)                                                     \
    asm volatile("mma.sync.aligned.m16n8k16.row.col.f32.f16.f16.f32 "       \
                 "{%0,%1,%2,%3}, {%4,%5,%6,%7}, {%8,%9}, {%0,%1,%2,%3};"    \
                 : "+f"((d)[0]), "+f"((d)[1]), "+f"((d)[2]), "+f"((d)[3])    \
                 : "r"((a)[0]), "r"((a)[1]), "r"((a)[2]), "r"((a)[3]),       \
                   "r"((b)[0]), "r"((b)[1]))

// ---------------- weight prep ----------------------------------------------
__global__ void build_wb_kernel(const float* __restrict__ w) {
    int idx = blockIdx.x * 256 + threadIdx.x;   // 55296 total
    if (idx >= 55296) return;
    int tap = idx >> 11;
    int r = idx & 2047;
    int half = r >> 10;
    int ic = (r >> 6) & 15;
    int oc = (half << 6) | (r & 63);
    g_wb2[idx] = __float2half_rn(w[oc * 432 + ic * 27 + tap]);
}

// ---------------- conv via warp MMA -----------------------------------------
// CTA: 128 positions (2z x 8y x 8x) x 128 oc. 8 warps: Wm=4 x Wn=2.
__global__ __launch_bounds__(256, 2)
void conv_mma_kernel(const float* __restrict__ x, const float* __restrict__ cb) {
    extern __shared__ char sm[];
    const u32 smb = smem_u32(sm);
    const int tid = threadIdx.x;
    const int wid = tid >> 5, lane = tid & 31;
    const int n = blockIdx.y, b = n >> 3, i = n & 7;
    const int tile = blockIdx.x;                 // 256 tiles: 4x*4y*16z
    const int x0 = (tile & 3) * 8;
    const int y0 = ((tile >> 2) & 3) * 8;
    const int z0 = (tile >> 4) * 2;

    const int wm = (wid >> 1) * 32;
    const int half = wid & 1;                    // oc half
    const int wn = half * 64;
    const u32 wbase = smb + OFF_B + (u32)wid * (NBUF * B_BUF);

    // ---- per-warp B staging: 4 x 16B per lane per tap (.ca: L1-resident) ----
    const int srow0 = lane >> 3, sseg = lane & 7;
    auto stage_tap = [&](int tap, int buf) {
        const __half* gsrc = g_wb2 + ((tap * 2 + half) << 10);
#pragma unroll
        for (int j = 0; j < 4; ++j) {
            int row = srow0 + j * 4;
            u32 d = wbase + (u32)buf * B_BUF + row * B_ROW + sseg * 16;
            const __half* s = gsrc + row * 64 + sseg * 8;
            asm volatile("cp.async.ca.shared.global [%0], [%1], 16;"
                         :: "r"(d), "l"(s));
        }
        asm volatile("cp.async.commit_group;" ::: "memory");
    };

    stage_tap(0, 0);
    stage_tap(1, 1);
    stage_tap(2, 2);

    // ---- halo tile: [400 rows][ic16] fp16, row stride 48B ----
    const float* xn = x + (size_t)n * 524288;
    for (int idx = tid; idx < 6400; idx += 256) {
        int ic = idx / 400, h = idx - ic * 400;
        int hz = h / 100, rp = h - hz * 100;
        int hy = rp / 10, hx = rp - hy * 10;
        int gz = z0 + hz - 1, gy = y0 + hy - 1, gx = x0 + hx - 1;
        float v = 0.0f;
        if ((unsigned)gz < 32u && (unsigned)gy < 32u && (unsigned)gx < 32u)
            v = xn[ic * 32768 + gz * 1024 + gy * 32 + gx];
        *(u16*)(sm + OFF_HH + h * 48 + ic * 2) =
            __half_as_ushort(__float2half_rn(v));
    }
    __syncthreads();

    // ---- per-lane ldmatrix addresses ----
    const int lr = lane & 15;
    const int ksel = (lane >> 4) * 16;
    u32 laddrA[2];
#pragma unroll
    for (int f = 0; f < 2; ++f) {
        int pos = wm + f * 16 + lr;
        int lz = pos >> 6, ly = (pos >> 3) & 7, lx = pos & 7;
        laddrA[f] = smb + OFF_HH + (lz * 100 + ly * 10 + lx) * 48 + ksel;
    }
    u32 baddr[4];
#pragma unroll
    for (int p = 0; p < 4; ++p) {
        int ncloc = p * 16 + ((lane >> 4) & 1) * 8;
        baddr[p] = wbase + (lane & 15) * B_ROW + ncloc * 2;
    }

    float acc[2][8][4];
#pragma unroll
    for (int f = 0; f < 2; ++f)
#pragma unroll
        for (int nf = 0; nf < 8; ++nf)
#pragma unroll
            for (int q = 0; q < 4; ++q) acc[f][nf][q] = 0.0f;

#pragma unroll 1
    for (int tap = 0; tap < 27; ++tap) {
        if (tap < 25) {
            asm volatile("cp.async.wait_group 2;" ::: "memory");
        } else if (tap == 25) {
            asm volatile("cp.async.wait_group 1;" ::: "memory");
        } else {
            asm volatile("cp.async.wait_group 0;" ::: "memory");
        }
        __syncwarp();

        const int dz = tap / 9;
        const int rm = tap - dz * 9;
        const int dy = rm / 3, dx = rm - dy * 3;
        const u32 delta = (u32)((dz * 100 + dy * 10 + dx) * 48);

        u32 ah[2][4];
        LDSM_X4(ah[0], laddrA[0] + delta);
        LDSM_X4(ah[1], laddrA[1] + delta);

        const u32 bufo = (u32)((tap & 3) * B_BUF);
#pragma unroll
        for (int p = 0; p < 4; ++p) {
            u32 b0, b1, b2, b3;
            LDSM_X4T(b0, b1, b2, b3, baddr[p] + bufo);
            u32 bb0[2] = {b0, b1}, bb1[2] = {b2, b3};
#pragma unroll
            for (int f = 0; f < 2; ++f) {
                MMA_F32(acc[f][p * 2], ah[f], bb0);
                MMA_F32(acc[f][p * 2 + 1], ah[f], bb1);
            }
        }

        if (tap + 3 < 27) stage_tap(tap + 3, (tap + 3) & 3);
    }

    // ---- epilogue: bias add, SMEM transpose, coalesced STG.128 ----
    float2 cbv[8];
#pragma unroll
    for (int nf = 0; nf < 8; ++nf)
        cbv[nf] = *(const float2*)(cb + wn + nf * 8 + (lane & 3) * 2);

    __syncthreads();   // all B-buffer reads done; reuse as staging
    // stage votes_sm[pos][oc] f16, row stride 272B (conflict-free)
#pragma unroll
    for (int f = 0; f < 2; ++f) {
#pragma unroll
        for (int hrow = 0; hrow < 2; ++hrow) {
            int pos = wm + f * 16 + (lane >> 2) + hrow * 8;
#pragma unroll
            for (int nf = 0; nf < 8; ++nf) {
                int col = wn + nf * 8 + (lane & 3) * 2;
                float ox = acc[f][nf][hrow * 2 + 0] + cbv[nf].x;
                float oy = acc[f][nf][hrow * 2 + 1] + cbv[nf].y;
                *(__half2*)(sm + OFF_B + pos * 272 + col * 2) =
                    __floats2half2_rn(ox, oy);
            }
        }
    }
    __syncthreads();

    // coalesced write-out: 16 lanes cover one 256B row, 8 rows per thread
    const int c16 = tid & 15;
    for (int r = tid >> 4; r < 128; r += 16) {
        uint4 v = *(uint4*)(sm + OFF_B + r * 272 + c16 * 16);
        int gpos = (z0 + (r >> 6)) * 1024 + (y0 + ((r >> 3) & 7)) * 32 +
                   (x0 + (r & 7));
        *(uint4*)(g_votesh + (size_t)(b * 32768 + gpos) * 1024 + i * 128 +
                  c16 * 8) = v;
    }
}

// ---------------- Routing kernel (half2 regs, 4 CTAs/SM) --------------------
__global__ __launch_bounds__(256, 4)
void routing_kernel(const float* __restrict__ biases,
                    float* __restrict__ out) {
    __shared__ float sf[8 * 132];

    const int tid  = threadIdx.x;
    const int wrp  = tid >> 5;
    const int lane = tid & 31;
    const int o = lane >> 2;
    const int g = lane & 3;
    const int blk = blockIdx.x;
    const int b = blk >> 12;
    const int posbase = (blk & 4095) << 3;
    const int pos = posbase + wrp;

    const uint2* vp =
        (const uint2*)(g_votesh + (size_t)(b * 32768 + pos) * 1024);

    __half2 v2[8][2];
    float vnsq[8];
#pragma unroll
    for (int in = 0; in < 8; ++in) {
        uint2 raw = vp[in * 32 + o * 4 + g];
        v2[in][0] = *(__half2*)&raw.x;
        v2[in][1] = *(__half2*)&raw.y;
        float2 f01 = __half22float2(v2[in][0]);
        float2 f23 = __half22float2(v2[in][1]);
        float s = f01.x * f01.x + f01.y * f01.y +
                  f23.x * f23.x + f23.y * f23.y;
        s += __shfl_xor_sync(0xffffffffu, s, 1);
        s += __shfl_xor_sync(0xffffffffu, s, 2);
        vnsq[in] = s;
    }
    const float4 bs = ((const float4*)biases)[o * 4 + g];

    float logit[8];
#pragma unroll
    for (int in = 0; in < 8; ++in) logit[in] = 0.0f;

    float p0, p1, p2, p3;
    for (int it = 0; it < 3; ++it) {
        float route[8];
        if (it == 0) {
#pragma unroll
            for (int in = 0; in < 8; ++in) route[in] = 0.125f;
        } else {
#pragma unroll
            for (int in = 0; in < 8; ++in) {
                float e = __expf(logit[in]);
                float s = e;
                s += __shfl_xor_sync(0xffffffffu, s, 4);
                s += __shfl_xor_sync(0xffffffffu, s, 8);
                s += __shfl_xor_sync(0xffffffffu, s, 16);
                route[in] = __fdividef(e, s);
            }
        }
        p0 = bs.x; p1 = bs.y; p2 = bs.z; p3 = bs.w;
#pragma unroll
        for (int in = 0; in < 8; ++in) {
            float2 f01 = __half22float2(v2[in][0]);
            float2 f23 = __half22float2(v2[in][1]);
            p0 = fmaf(route[in], f01.x, p0);
            p1 = fmaf(route[in], f01.y, p1);
            p2 = fmaf(route[in], f23.x, p2);
            p3 = fmaf(route[in], f23.y, p3);
        }
        if (it < 2) {
            float pnsq = p0 * p0 + p1 * p1 + p2 * p2 + p3 * p3;
            pnsq += __shfl_xor_sync(0xffffffffu, pnsq, 1);
            pnsq += __shfl_xor_sync(0xffffffffu, pnsq, 2);
#pragma unroll
            for (int in = 0; in < 8; ++in) {
                float2 f01 = __half22float2(v2[in][0]);
                float2 f23 = __half22float2(v2[in][1]);
                float d = p0 * f01.x + p1 * f01.y + p2 * f23.x + p3 * f23.y;
                d += __shfl_xor_sync(0xffffffffu, d, 1);
                d += __shfl_xor_sync(0xffffffffu, d, 2);
                logit[in] = fmaf(
                    d, rsqrtf(fmaxf(pnsq * vnsq[in], 1e-16f)), logit[in]);
            }
        }
    }

    float nsq = p0 * p0 + p1 * p1 + p2 * p2 + p3 * p3;
    nsq += __shfl_xor_sync(0xffffffffu, nsq, 1);
    nsq += __shfl_xor_sync(0xffffffffu, nsq, 2);
    const float nrm = sqrtf(nsq);
    const float scale = __fdividef(nsq, (1.0f + nsq) * (nrm + 1e-12f));

    ((float4*)sf)[wrp * 33 + (o * 4 + g)] =
        make_float4(p0 * scale, p1 * scale, p2 * scale, p3 * scale);
    __syncthreads();

    for (int j = tid; j < 1024; j += 256) {
        const int oa = j >> 3;
        const int pp = j & 7;
        out[(size_t)(b * 128 + oa) * 32768 + posbase + pp] = sf[pp * 132 + oa];
    }
}

// ---------------- Launch -----------------------------------------------------
extern "C" void kernel_launch(void* const* d_in, const int* in_sizes, int n_in,
                              void* d_out, int out_size) {
    const float* x      = (const float*)d_in[0];
    const float* w      = (const float*)d_in[1];
    const float* cb     = (const float*)d_in[2];
    const float* biases = (const float*)d_in[3];
    float* out = (float*)d_out;

    build_wb_kernel<<<216, 256>>>(w);

    cudaFuncSetAttribute(conv_mma_kernel,
                         cudaFuncAttributeMaxDynamicSharedMemorySize,
                         CONV_SMEM);
    conv_mma_kernel<<<dim3(256, 16), 256, CONV_SMEM>>>(x, cb);
    routing_kernel<<<8192, 256>>>(biases, out);
}

// round 15
// speedup vs baseline: 1.4961x; 1.0510x over previous
#include <cuda_runtime.h>
#include <cuda_fp16.h>
#include <math.h>

typedef unsigned int u32;
typedef unsigned short u16;

// ---------------------------------------------------------------------------
// ConvSlimCapsule3D via warp-level fp16 MMA (single-term, fp32 acc)
// + 2-position-per-warp fast-math routing. Votes stored fp16.
// x(2,8,16,32,32,32) w(128,16,3,3,3) cb(128) biases(8,16,1,1,1)
// ---------------------------------------------------------------------------

__device__ __half g_votesh[67108864];        // [b][pos][i*128+oc], 128 MB
// weights fp16: [tap=27][half=2][ic=16][oc=64]
__device__ __align__(16) __half g_wb2[55296];

// ---- SMEM layout (bytes) ----
#define OFF_HH 0
#define OFF_B  19200
#define B_ROW  144           // 16B-aligned rows; 144%128=16 -> conflict-free
#define B_BUF  (16 * B_ROW)  // 2304
#define NBUF   4
#define CONV_SMEM (19200 + 8 * NBUF * B_BUF)   // 92928

__device__ __forceinline__ u32 smem_u32(const void* p) {
    u32 a;
    asm("{ .reg .u64 t; cvta.to.shared.u64 t, %1; cvt.u32.u64 %0, t; }"
        : "=r"(a) : "l"(p));
    return a;
}

#define LDSM_X4(r, a)                                                        \
    asm volatile("ldmatrix.sync.aligned.m8n8.x4.shared.b16 "                 \
                 "{%0,%1,%2,%3}, [%4];"                                      \
                 : "=r"((r)[0]), "=r"((r)[1]), "=r"((r)[2]), "=r"((r)[3])    \
                 : "r"(a))
#define LDSM_X4T(r0, r1, r2, r3, a)                                          \
    asm volatile("ldmatrix.sync.aligned.m8n8.x4.trans.shared.b16 "           \
                 "{%0,%1,%2,%3}, [%4];"                                      \
                 : "=r"(r0), "=r"(r1), "=r"(r2), "=r"(r3) : "r"(a))
#define MMA_F32(d, a, b)                                                     \
    asm volatile("mma.sync.aligned.m16n8k16.row.col.f32.f16.f16.f32 "       \
                 "{%0,%1,%2,%3}, {%4,%5,%6,%7}, {%8,%9}, {%0,%1,%2,%3};"    \
                 : "+f"((d)[0]), "+f"((d)[1]), "+f"((d)[2]), "+f"((d)[3])    \
                 : "r"((a)[0]), "r"((a)[1]), "r"((a)[2]), "r"((a)[3]),       \
                   "r"((b)[0]), "r"((b)[1]))

// ---------------- weight prep ----------------------------------------------
__global__ void build_wb_kernel(const float* __restrict__ w) {
    int idx = blockIdx.x * 256 + threadIdx.x;   // 55296 total
    if (idx >= 55296) return;
    int tap = idx >> 11;
    int r = idx & 2047;
    int half = r >> 10;
    int ic = (r >> 6) & 15;
    int oc = (half << 6) | (r & 63);
    g_wb2[idx] = __float2half_rn(w[oc * 432 + ic * 27 + tap]);
}

// ---------------- conv via warp MMA (unchanged from R14 winner) -------------
__global__ __launch_bounds__(256, 2)
void conv_mma_kernel(const float* __restrict__ x, const float* __restrict__ cb) {
    extern __shared__ char sm[];
    const u32 smb = smem_u32(sm);
    const int tid = threadIdx.x;
    const int wid = tid >> 5, lane = tid & 31;
    const int n = blockIdx.y, b = n >> 3, i = n & 7;
    const int tile = blockIdx.x;                 // 256 tiles: 4x*4y*16z
    const int x0 = (tile & 3) * 8;
    const int y0 = ((tile >> 2) & 3) * 8;
    const int z0 = (tile >> 4) * 2;

    const int wm = (wid >> 1) * 32;
    const int half = wid & 1;                    // oc half
    const int wn = half * 64;
    const u32 wbase = smb + OFF_B + (u32)wid * (NBUF * B_BUF);

    const int srow0 = lane >> 3, sseg = lane & 7;
    auto stage_tap = [&](int tap, int buf) {
        const __half* gsrc = g_wb2 + ((tap * 2 + half) << 10);
#pragma unroll
        for (int j = 0; j < 4; ++j) {
            int row = srow0 + j * 4;
            u32 d = wbase + (u32)buf * B_BUF + row * B_ROW + sseg * 16;
            const __half* s = gsrc + row * 64 + sseg * 8;
            asm volatile("cp.async.ca.shared.global [%0], [%1], 16;"
                         :: "r"(d), "l"(s));
        }
        asm volatile("cp.async.commit_group;" ::: "memory");
    };

    stage_tap(0, 0);
    stage_tap(1, 1);
    stage_tap(2, 2);

    const float* xn = x + (size_t)n * 524288;
    for (int idx = tid; idx < 6400; idx += 256) {
        int ic = idx / 400, h = idx - ic * 400;
        int hz = h / 100, rp = h - hz * 100;
        int hy = rp / 10, hx = rp - hy * 10;
        int gz = z0 + hz - 1, gy = y0 + hy - 1, gx = x0 + hx - 1;
        float v = 0.0f;
        if ((unsigned)gz < 32u && (unsigned)gy < 32u && (unsigned)gx < 32u)
            v = xn[ic * 32768 + gz * 1024 + gy * 32 + gx];
        *(u16*)(sm + OFF_HH + h * 48 + ic * 2) =
            __half_as_ushort(__float2half_rn(v));
    }
    __syncthreads();

    const int lr = lane & 15;
    const int ksel = (lane >> 4) * 16;
    u32 laddrA[2];
#pragma unroll
    for (int f = 0; f < 2; ++f) {
        int pos = wm + f * 16 + lr;
        int lz = pos >> 6, ly = (pos >> 3) & 7, lx = pos & 7;
        laddrA[f] = smb + OFF_HH + (lz * 100 + ly * 10 + lx) * 48 + ksel;
    }
    u32 baddr[4];
#pragma unroll
    for (int p = 0; p < 4; ++p) {
        int ncloc = p * 16 + ((lane >> 4) & 1) * 8;
        baddr[p] = wbase + (lane & 15) * B_ROW + ncloc * 2;
    }

    float acc[2][8][4];
#pragma unroll
    for (int f = 0; f < 2; ++f)
#pragma unroll
        for (int nf = 0; nf < 8; ++nf)
#pragma unroll
            for (int q = 0; q < 4; ++q) acc[f][nf][q] = 0.0f;

#pragma unroll 1
    for (int tap = 0; tap < 27; ++tap) {
        if (tap < 25) {
            asm volatile("cp.async.wait_group 2;" ::: "memory");
        } else if (tap == 25) {
            asm volatile("cp.async.wait_group 1;" ::: "memory");
        } else {
            asm volatile("cp.async.wait_group 0;" ::: "memory");
        }
        __syncwarp();

        const int dz = tap / 9;
        const int rm = tap - dz * 9;
        const int dy = rm / 3, dx = rm - dy * 3;
        const u32 delta = (u32)((dz * 100 + dy * 10 + dx) * 48);

        u32 ah[2][4];
        LDSM_X4(ah[0], laddrA[0] + delta);
        LDSM_X4(ah[1], laddrA[1] + delta);

        const u32 bufo = (u32)((tap & 3) * B_BUF);
#pragma unroll
        for (int p = 0; p < 4; ++p) {
            u32 b0, b1, b2, b3;
            LDSM_X4T(b0, b1, b2, b3, baddr[p] + bufo);
            u32 bb0[2] = {b0, b1}, bb1[2] = {b2, b3};
#pragma unroll
            for (int f = 0; f < 2; ++f) {
                MMA_F32(acc[f][p * 2], ah[f], bb0);
                MMA_F32(acc[f][p * 2 + 1], ah[f], bb1);
            }
        }

        if (tap + 3 < 27) stage_tap(tap + 3, (tap + 3) & 3);
    }

    // ---- epilogue: bias add, SMEM transpose, coalesced STG.128 ----
    float2 cbv[8];
#pragma unroll
    for (int nf = 0; nf < 8; ++nf)
        cbv[nf] = *(const float2*)(cb + wn + nf * 8 + (lane & 3) * 2);

    __syncthreads();
#pragma unroll
    for (int f = 0; f < 2; ++f) {
#pragma unroll
        for (int hrow = 0; hrow < 2; ++hrow) {
            int pos = wm + f * 16 + (lane >> 2) + hrow * 8;
#pragma unroll
            for (int nf = 0; nf < 8; ++nf) {
                int col = wn + nf * 8 + (lane & 3) * 2;
                float ox = acc[f][nf][hrow * 2 + 0] + cbv[nf].x;
                float oy = acc[f][nf][hrow * 2 + 1] + cbv[nf].y;
                *(__half2*)(sm + OFF_B + pos * 272 + col * 2) =
                    __floats2half2_rn(ox, oy);
            }
        }
    }
    __syncthreads();

    const int c16 = tid & 15;
    for (int r = tid >> 4; r < 128; r += 16) {
        uint4 v = *(uint4*)(sm + OFF_B + r * 272 + c16 * 16);
        int gpos = (z0 + (r >> 6)) * 1024 + (y0 + ((r >> 3) & 7)) * 32 +
                   (x0 + (r & 7));
        *(uint4*)(g_votesh + (size_t)(b * 32768 + gpos) * 1024 + i * 128 +
                  c16 * 8) = v;
    }
}

// ---------------- Routing kernel: 2 positions per warp ----------------------
// lane = ph*16 + o*2 + gg : ph = position within warp pair, o = out capsule,
// gg selects atoms [gg*8, gg*8+8). Votes -> fp32 registers once (no repeated
// F2F). Block = 8 warps = 16 positions.
__global__ __launch_bounds__(256, 2)
void routing_kernel(const float* __restrict__ biases,
                    float* __restrict__ out) {
    __shared__ float sf[16 * 132];

    const int tid  = threadIdx.x;
    const int wrp  = tid >> 5;
    const int lane = tid & 31;
    const int ph = lane >> 4;
    const int o  = (lane >> 1) & 7;
    const int gg = lane & 1;
    const int blk = blockIdx.x;
    const int b = blk >> 11;                 // 2048 blocks per batch
    const int posbase = (blk & 2047) << 4;   // 16 positions per block
    const int pos = posbase + wrp * 2 + ph;
    const int slocal = wrp * 2 + ph;

    const uint4* vp =
        (const uint4*)(g_votesh + (size_t)(b * 32768 + pos) * 1024);

    float v[8][8];
    float rv[8];
#pragma unroll
    for (int in = 0; in < 8; ++in) {
        uint4 raw = vp[in * 16 + o * 2 + gg];
        const __half2* h = (const __half2*)&raw;
        float2 f0 = __half22float2(h[0]);
        float2 f1 = __half22float2(h[1]);
        float2 f2 = __half22float2(h[2]);
        float2 f3 = __half22float2(h[3]);
        v[in][0] = f0.x; v[in][1] = f0.y; v[in][2] = f1.x; v[in][3] = f1.y;
        v[in][4] = f2.x; v[in][5] = f2.y; v[in][6] = f3.x; v[in][7] = f3.y;
        float s = 0.0f;
#pragma unroll
        for (int k = 0; k < 8; ++k) s = fmaf(v[in][k], v[in][k], s);
        s += __shfl_xor_sync(0xffffffffu, s, 1);
        rv[in] = rsqrtf(fmaxf(s, 1e-24f));
    }

    const float4* bp = (const float4*)(biases + o * 16 + gg * 8);
    float4 bs0 = bp[0], bs1 = bp[1];
    float bsv[8] = {bs0.x, bs0.y, bs0.z, bs0.w, bs1.x, bs1.y, bs1.z, bs1.w};

    float logit[8];
#pragma unroll
    for (int in = 0; in < 8; ++in) logit[in] = 0.0f;

    float p[8];
    for (int it = 0; it < 3; ++it) {
        float route[8];
        if (it == 0) {
#pragma unroll
            for (int in = 0; in < 8; ++in) route[in] = 0.125f;
        } else {
#pragma unroll
            for (int in = 0; in < 8; ++in) {
                float e = __expf(logit[in]);
                float s = e;
                s += __shfl_xor_sync(0xffffffffu, s, 2);
                s += __shfl_xor_sync(0xffffffffu, s, 4);
                s += __shfl_xor_sync(0xffffffffu, s, 8);
                route[in] = __fdividef(e, s);
            }
        }
#pragma unroll
        for (int k = 0; k < 8; ++k) p[k] = bsv[k];
#pragma unroll
        for (int in = 0; in < 8; ++in)
#pragma unroll
            for (int k = 0; k < 8; ++k)
                p[k] = fmaf(route[in], v[in][k], p[k]);

        if (it < 2) {
            float pn = 0.0f;
#pragma unroll
            for (int k = 0; k < 8; ++k) pn = fmaf(p[k], p[k], pn);
            pn += __shfl_xor_sync(0xffffffffu, pn, 1);
            float rpn = rsqrtf(fmaxf(pn, 1e-24f));
#pragma unroll
            for (int in = 0; in < 8; ++in) {
                float d = 0.0f;
#pragma unroll
                for (int k = 0; k < 8; ++k) d = fmaf(p[k], v[in][k], d);
                d += __shfl_xor_sync(0xffffffffu, d, 1);
                logit[in] = fmaf(d * rv[in], rpn, logit[in]);
            }
        }
    }

    // squash over the 16 atoms
    float nsq = 0.0f;
#pragma unroll
    for (int k = 0; k < 8; ++k) nsq = fmaf(p[k], p[k], nsq);
    nsq += __shfl_xor_sync(0xffffffffu, nsq, 1);
    const float nrm = sqrtf(nsq);
    const float scale = __fdividef(nsq, (1.0f + nsq) * (nrm + 1e-12f));

    float* sfr = sf + slocal * 132 + o * 16 + gg * 8;
    ((float4*)sfr)[0] =
        make_float4(p[0] * scale, p[1] * scale, p[2] * scale, p[3] * scale);
    ((float4*)sfr)[1] =
        make_float4(p[4] * scale, p[5] * scale, p[6] * scale, p[7] * scale);
    __syncthreads();

    // out[(b*128 + oa)*32768 + pos], coalesced 64B runs over 16 positions
    for (int j = tid; j < 2048; j += 256) {
        const int oa = j >> 4;
        const int pp = j & 15;
        out[(size_t)(b * 128 + oa) * 32768 + posbase + pp] = sf[pp * 132 + oa];
    }
}

// ---------------- Launch -----------------------------------------------------
extern "C" void kernel_launch(void* const* d_in, const int* in_sizes, int n_in,
                              void* d_out, int out_size) {
    const float* x      = (const float*)d_in[0];
    const float* w      = (const float*)d_in[1];
    const float* cb     = (const float*)d_in[2];
    const float* biases = (const float*)d_in[3];
    float* out = (float*)d_out;

    build_wb_kernel<<<216, 256>>>(w);

    cudaFuncSetAttribute(conv_mma_kernel,
                         cudaFuncAttributeMaxDynamicSharedMemorySize,
                         CONV_SMEM);
    conv_mma_kernel<<<dim3(256, 16), 256, CONV_SMEM>>>(x, cb);
    routing_kernel<<<4096, 256>>>(biases, out);
}